// round 2
// baseline (speedup 1.0000x reference)
#include <cuda_runtime.h>
#include <math.h>

#define BB 64
#define TT 20
#define CC 512
#define HWD 196
#define VV 10000
#define EE 256
#define UU 512
#define G4 2048            // 4*U
#define XD 1280            // E + C + U  (also U + C + E for outs)
#define IHK 768            // C + E (W_ih inner dim)
#define LOGITS_SZ (BB*TT*VV)
#define ATTN_SZ (BB*TT*HWD)

// ---------------- device scratch (static: no allocations allowed) ----------
__device__ float g_featsT[(size_t)BB*HWD*CC];   // [B, HW, C]
__device__ float g_fm[BB*CC];                   // [B, C] mean feats
__device__ float g_keys[(size_t)BB*HWD*UU];     // [B, HW, U]
__device__ float g_hid[BB*UU];
__device__ float g_cell[BB*UU];
__device__ float g_capemb[(size_t)BB*TT*EE];    // [B, T, E]
__device__ float g_w[BB*HWD];                   // scores / softmax weights
__device__ float g_x[BB*XD];                    // [emb | a | hid]
__device__ float g_gates[BB*G4];
__device__ float g_outs[(size_t)BB*TT*XD];      // [hid | a | emb]
__device__ float g_Wcat[(size_t)G4*XD];         // [W_ih | W_hh]
__device__ float g_bcat[G4];

// ---------------- kernels --------------------------------------------------

// mean over HW: one warp per (b,c)
__global__ void mean_kernel(const float* __restrict__ img) {
    int w = (blockIdx.x * blockDim.x + threadIdx.x) >> 5;
    int lane = threadIdx.x & 31;
    if (w >= BB * CC) return;
    const float* p = img + (size_t)w * HWD;
    float s = 0.f;
    for (int k = lane; k < HWD; k += 32) s += p[k];
    #pragma unroll
    for (int o = 16; o; o >>= 1) s += __shfl_xor_sync(0xFFFFFFFFu, s, o);
    if (!lane) g_fm[w] = s * (1.0f / HWD);
}

// featsT[b][k][c] = img[b][c][k]
__global__ void transpose_kernel(const float* __restrict__ img) {
    __shared__ float tile[32][33];
    int b = blockIdx.z;
    int k0 = blockIdx.x * 32, c0 = blockIdx.y * 32;
    int tx = threadIdx.x, ty = threadIdx.y;   // 32 x 8
    for (int i = ty; i < 32; i += 8) {
        int c = c0 + i, k = k0 + tx;
        tile[i][tx] = (c < CC && k < HWD) ? img[((size_t)b * CC + c) * HWD + k] : 0.f;
    }
    __syncthreads();
    for (int i = ty; i < 32; i += 8) {
        int k = k0 + i, c = c0 + tx;
        if (k < HWD && c < CC)
            g_featsT[((size_t)b * HWD + k) * CC + c] = tile[tx][i];
    }
}

// hid0/cell0: one warp per (b,u)
__global__ void init_hc_kernel(const float* __restrict__ W_h0, const float* __restrict__ b_h0,
                               const float* __restrict__ W_c0, const float* __restrict__ b_c0) {
    int w = (blockIdx.x * blockDim.x + threadIdx.x) >> 5;
    int lane = threadIdx.x & 31;
    if (w >= BB * UU) return;
    int b = w / UU, u = w % UU;
    const float* fm = g_fm + b * CC;
    const float* wh = W_h0 + (size_t)u * CC;
    const float* wc = W_c0 + (size_t)u * CC;
    float sh = 0.f, sc = 0.f;
    for (int c = lane; c < CC; c += 32) {
        float f = fm[c];
        sh += f * wh[c];
        sc += f * wc[c];
    }
    #pragma unroll
    for (int o = 16; o; o >>= 1) {
        sh += __shfl_xor_sync(0xFFFFFFFFu, sh, o);
        sc += __shfl_xor_sync(0xFFFFFFFFu, sc, o);
    }
    if (!lane) {
        g_hid[w]  = sh + b_h0[u];
        g_cell[w] = sc + b_c0[u];
    }
}

// embedding gather with max_norm=5: one warp per (b,t)
__global__ void emb_kernel(const int* __restrict__ cap, const float* __restrict__ emb) {
    int w = (blockIdx.x * blockDim.x + threadIdx.x) >> 5;
    int lane = threadIdx.x & 31;
    if (w >= BB * TT) return;
    int idx = cap[w];
    const float* row = emb + (size_t)idx * EE;
    float v[8];
    float ss = 0.f;
    #pragma unroll
    for (int i = 0; i < 8; i++) { v[i] = row[lane + 32 * i]; ss += v[i] * v[i]; }
    #pragma unroll
    for (int o = 16; o; o >>= 1) ss += __shfl_xor_sync(0xFFFFFFFFu, ss, o);
    float norm = sqrtf(ss);
    float sc = fminf(1.0f, 5.0f / fmaxf(norm, 1e-12f));
    #pragma unroll
    for (int i = 0; i < 8; i++) g_capemb[(size_t)w * EE + lane + 32 * i] = v[i] * sc;
}

// concat [W_ih | W_hh] -> Wcat, b_ih + b_hh -> bcat
__global__ void wcat_kernel(const float* __restrict__ W_ih, const float* __restrict__ b_ih,
                            const float* __restrict__ W_hh, const float* __restrict__ b_hh) {
    int stride = gridDim.x * blockDim.x;
    int t0 = blockIdx.x * blockDim.x + threadIdx.x;
    for (int i = t0; i < G4 * XD; i += stride) {
        int j = i / XD, c = i - j * XD;
        g_Wcat[i] = (c < IHK) ? W_ih[(size_t)j * IHK + c]
                              : W_hh[(size_t)j * UU + (c - IHK)];
    }
    if (t0 < G4) g_bcat[t0] = b_ih[t0] + b_hh[t0];
}

// Generic fp32 NT GEMM:  C[m,n] = sum_k A[m,k]*B[n,k] + bias[n]
// BM=BN=64, BK=16, 256 threads, 4x4 per thread. K % 16 == 0, lda/ldb % 4 == 0.
__global__ void __launch_bounds__(256) gemm_nt(
    const float* __restrict__ A, int lda,
    const float* __restrict__ Bm, int ldb,
    const float* __restrict__ bias,
    float* __restrict__ Cm, int ldc,
    int M, int N, int K)
{
    __shared__ float As[16][64];
    __shared__ float Bs[16][64];
    int tid = threadIdx.x;
    int m0 = blockIdx.y * 64, n0 = blockIdx.x * 64;
    int ty = tid >> 4, tx = tid & 15;
    int lrow = tid >> 2, lq = tid & 3;
    float acc[4][4] = {};
    const float* Ap = A + (size_t)(m0 + lrow) * lda + lq * 4;
    const float* Bp = Bm + (size_t)(n0 + lrow) * ldb + lq * 4;
    bool aval = (m0 + lrow) < M;
    bool bval = (n0 + lrow) < N;

    for (int k0 = 0; k0 < K; k0 += 16) {
        float4 av = aval ? *(const float4*)(Ap + k0) : make_float4(0.f, 0.f, 0.f, 0.f);
        float4 bv = bval ? *(const float4*)(Bp + k0) : make_float4(0.f, 0.f, 0.f, 0.f);
        __syncthreads();
        As[lq * 4 + 0][lrow] = av.x; As[lq * 4 + 1][lrow] = av.y;
        As[lq * 4 + 2][lrow] = av.z; As[lq * 4 + 3][lrow] = av.w;
        Bs[lq * 4 + 0][lrow] = bv.x; Bs[lq * 4 + 1][lrow] = bv.y;
        Bs[lq * 4 + 2][lrow] = bv.z; Bs[lq * 4 + 3][lrow] = bv.w;
        __syncthreads();
        #pragma unroll
        for (int kk = 0; kk < 16; kk++) {
            float4 a4 = *(const float4*)(&As[kk][ty * 4]);
            float4 b4 = *(const float4*)(&Bs[kk][tx * 4]);
            float ar[4] = {a4.x, a4.y, a4.z, a4.w};
            float br[4] = {b4.x, b4.y, b4.z, b4.w};
            #pragma unroll
            for (int i = 0; i < 4; i++)
                #pragma unroll
                for (int j = 0; j < 4; j++)
                    acc[i][j] += ar[i] * br[j];
        }
    }
    #pragma unroll
    for (int i = 0; i < 4; i++) {
        int m = m0 + ty * 4 + i;
        if (m < M) {
            #pragma unroll
            for (int j = 0; j < 4; j++) {
                int n = n0 + tx * 4 + j;
                if (n < N) Cm[(size_t)m * ldc + n] = acc[i][j] + bias[n];
            }
        }
    }
}

// attention scores: one warp per (b,k)
__global__ void scores_kernel() {
    int w = (blockIdx.x * blockDim.x + threadIdx.x) >> 5;
    int lane = threadIdx.x & 31;
    if (w >= BB * HWD) return;
    int b = w / HWD;
    const float* h  = g_hid + b * UU;
    const float* kp = g_keys + (size_t)w * UU;
    float s = 0.f;
    for (int u = lane; u < UU; u += 32) s += h[u] * kp[u];
    #pragma unroll
    for (int o = 16; o; o >>= 1) s += __shfl_xor_sync(0xFFFFFFFFu, s, o);
    if (!lane) g_w[w] = s * 0.044194173824159216f;  // 1/sqrt(512)
}

// softmax over HW per batch; also writes attn output
__global__ void softmax_kernel(float* __restrict__ attn_out, int t) {
    __shared__ float red[256];
    int b = blockIdx.x, tid = threadIdx.x;
    float v = (tid < HWD) ? g_w[b * HWD + tid] : -1e30f;
    red[tid] = v;
    __syncthreads();
    for (int s = 128; s; s >>= 1) { if (tid < s) red[tid] = fmaxf(red[tid], red[tid + s]); __syncthreads(); }
    float mx = red[0];
    __syncthreads();
    float e = (tid < HWD) ? expf(v - mx) : 0.f;
    red[tid] = e;
    __syncthreads();
    for (int s = 128; s; s >>= 1) { if (tid < s) red[tid] += red[tid + s]; __syncthreads(); }
    float inv = 1.0f / red[0];
    if (tid < HWD) {
        float wv = e * inv;
        g_w[b * HWD + tid] = wv;
        if (attn_out) attn_out[((size_t)b * TT + t) * HWD + tid] = wv;
    }
}

// a[b,c] = sum_k w[b,k]*img[b,c,k]; one warp per (b,c). Writes x and outs.
__global__ void attend_kernel(const float* __restrict__ img, int t) {
    int w = (blockIdx.x * blockDim.x + threadIdx.x) >> 5;
    int lane = threadIdx.x & 31;
    if (w >= BB * CC) return;
    int b = w / CC, c = w % CC;
    const float* wp = g_w + b * HWD;
    const float* ip = img + (size_t)w * HWD;
    float s = 0.f;
    for (int k = lane; k < HWD; k += 32) s += wp[k] * ip[k];
    #pragma unroll
    for (int o = 16; o; o >>= 1) s += __shfl_xor_sync(0xFFFFFFFFu, s, o);
    if (!lane) {
        g_x[b * XD + EE + c] = s;                                  // x = [emb | a | hid]
        g_outs[((size_t)(b * TT + t)) * XD + UU + c] = s;          // outs = [hid | a | emb]
    }
}

// pack emb_t + hid into x, emb_t into outs
__global__ void pack_kernel(int t) {
    int i = blockIdx.x * blockDim.x + threadIdx.x;
    if (i >= BB * (EE + UU)) return;
    int b = i / (EE + UU), r = i - b * (EE + UU);
    if (r < EE) {
        float e = g_capemb[((size_t)(b * TT + t)) * EE + r];
        g_x[b * XD + r] = e;
        g_outs[((size_t)(b * TT + t)) * XD + UU + CC + r] = e;
    } else {
        int u = r - EE;
        g_x[b * XD + IHK + u] = g_hid[b * UU + u];
    }
}

// LSTM pointwise update
__global__ void lstm_kernel(int t) {
    int i = blockIdx.x * blockDim.x + threadIdx.x;
    if (i >= BB * UU) return;
    int b = i / UU, u = i - b * UU;
    const float* gr = g_gates + (size_t)b * G4;
    float ig = gr[u], fg = gr[UU + u], gg = gr[2 * UU + u], og = gr[3 * UU + u];
    float si = 1.f / (1.f + expf(-ig));
    float sf = 1.f / (1.f + expf(-fg));
    float so = 1.f / (1.f + expf(-og));
    float c = sf * g_cell[i] + si * tanhf(gg);
    float h = so * tanhf(c);
    g_cell[i] = c;
    g_hid[i]  = h;
    g_outs[((size_t)(b * TT + t)) * XD + u] = h;
}

// ---------------- host launch ----------------------------------------------

static float* symaddr(const void* sym) {
    void* p = nullptr;
    cudaGetSymbolAddress(&p, sym);
    return (float*)p;
}

extern "C" void kernel_launch(void* const* d_in, const int* in_sizes, int n_in,
                              void* d_out, int out_size) {
    const float* img   = (const float*)d_in[0];
    const int*   cap   = (const int*)d_in[1];
    const float* W_h0  = (const float*)d_in[2];
    const float* b_h0  = (const float*)d_in[3];
    const float* W_c0  = (const float*)d_in[4];
    const float* b_c0  = (const float*)d_in[5];
    const float* emb   = (const float*)d_in[6];
    const float* W_key = (const float*)d_in[7];
    const float* b_key = (const float*)d_in[8];
    const float* W_ih  = (const float*)d_in[9];
    const float* b_ih  = (const float*)d_in[10];
    const float* W_hh  = (const float*)d_in[11];
    const float* b_hh  = (const float*)d_in[12];
    const float* W_out = (const float*)d_in[13];
    const float* b_out = (const float*)d_in[14];
    float* out = (float*)d_out;

    float* p_featsT = symaddr(g_featsT);
    float* p_keys   = symaddr(g_keys);
    float* p_x      = symaddr(g_x);
    float* p_gates  = symaddr(g_gates);
    float* p_outs   = symaddr(g_outs);
    float* p_Wcat   = symaddr(g_Wcat);
    float* p_bcat   = symaddr(g_bcat);

    float* attn_out = (out_size >= LOGITS_SZ + ATTN_SZ) ? (out + LOGITS_SZ) : nullptr;

    mean_kernel<<<(BB * CC / 8), 256>>>(img);
    transpose_kernel<<<dim3(7, 16, BB), dim3(32, 8)>>>(img);
    init_hc_kernel<<<(BB * UU / 8), 256>>>(W_h0, b_h0, W_c0, b_c0);
    emb_kernel<<<(BB * TT + 7) / 8, 256>>>(cap, emb);
    wcat_kernel<<<1024, 256>>>(W_ih, b_ih, W_hh, b_hh);

    // keys = featsT @ W_key^T + b_key : M=12544, N=512, K=512
    gemm_nt<<<dim3(UU / 64, (BB * HWD) / 64), 256>>>(
        p_featsT, CC, W_key, CC, b_key, p_keys, UU, BB * HWD, UU, CC);

    for (int t = 0; t < TT; t++) {
        scores_kernel<<<(BB * HWD + 7) / 8, 256>>>();
        softmax_kernel<<<BB, 256>>>(attn_out, t);
        attend_kernel<<<(BB * CC / 8), 256>>>(img, t);
        pack_kernel<<<(BB * (EE + UU) + 255) / 256, 256>>>(t);
        // gates = x @ Wcat^T + bcat : M=64, N=2048, K=1280
        gemm_nt<<<dim3(G4 / 64, 1), 256>>>(
            p_x, XD, p_Wcat, XD, p_bcat, p_gates, G4, BB, G4, XD);
        lstm_kernel<<<(BB * UU + 255) / 256, 256>>>(t);
    }

    // logits = outs @ W_out^T + b_out : M=1280, N=10000, K=1280
    gemm_nt<<<dim3((VV + 63) / 64, (BB * TT) / 64), 256>>>(
        p_outs, XD, W_out, XD, b_out, out, VV, BB * TT, VV, XD);
}

// round 4
// speedup vs baseline: 1.0287x; 1.0287x over previous
#include <cuda_runtime.h>
#include <cuda_bf16.h>
#include <math.h>
#include <stdint.h>

#define BB 64
#define TT 20
#define CC 512
#define HWD 196
#define VV 10000
#define EE 256
#define UU 512
#define G4 2048            // 4*U
#define XD 1280            // E + C + U
#define IHK 768            // C + E
#define LOGITS_SZ (BB*TT*VV)
#define ATTN_SZ (BB*TT*HWD)
#define KSPLIT 4

#define KT 32              // K-tile (bf16 elems)
#define APAD 36            // padded smem row stride (bf16 units) => 72B, conflict<=2-way

// ---------------- device scratch ----------------
__device__ float g_featsT[(size_t)BB*HWD*CC];   // [B, HW, C]
__device__ float g_fm[BB*CC];
__device__ float g_keys[(size_t)BB*HWD*UU];     // [B, HW, U]
__device__ float g_hid[BB*UU];
__device__ float g_cell[BB*UU];
__device__ float g_capemb[(size_t)BB*TT*EE];
__device__ float g_x[BB*XD];                    // [emb | a | hid]
__device__ float g_gpart[(size_t)KSPLIT*BB*G4]; // split-K partials
__device__ float g_outs[(size_t)BB*TT*XD];      // [hid | a | emb]
__device__ float g_Wcat[(size_t)G4*XD];
__device__ float g_bcat[G4];

// ---------------- helpers ----------------
__device__ __forceinline__ uint32_t packbf(float a, float b) {
    __nv_bfloat162 t = __floats2bfloat162_rn(a, b);
    return *(uint32_t*)&t;
}
__device__ __forceinline__ float bflo(uint32_t u) {
    __nv_bfloat162 t = *(__nv_bfloat162*)&u;
    return __low2float(t);
}
__device__ __forceinline__ float bfhi(uint32_t u) {
    __nv_bfloat162 t = *(__nv_bfloat162*)&u;
    return __high2float(t);
}
__device__ __forceinline__ void mma16816(float* c, const uint32_t* a, const uint32_t* b) {
    asm volatile(
        "mma.sync.aligned.m16n8k16.row.col.f32.bf16.bf16.f32 "
        "{%0,%1,%2,%3}, {%4,%5,%6,%7}, {%8,%9}, {%0,%1,%2,%3};"
        : "+f"(c[0]), "+f"(c[1]), "+f"(c[2]), "+f"(c[3])
        : "r"(a[0]), "r"(a[1]), "r"(a[2]), "r"(a[3]), "r"(b[0]), "r"(b[1]));
}

// ============================================================================
// HMMA bf16-split NT GEMM:  C[m,n] = sum_k A[m,k]*B[n,k] (+ bias[n])
// Tile 128x128, K-tile 32. grid = (ceil(N/128), ceil(M/128), nsplit).
// nsplit>1: writes partials at C + z*M*ldc (bias must be nullptr). K%(32*nsplit)==0.
// ============================================================================
__global__ void __launch_bounds__(256) hgemm(
    const float* __restrict__ A, int lda,
    const float* __restrict__ Bm, int ldb,
    const float* __restrict__ bias,
    float* __restrict__ Cm, int ldc,
    int M, int N, int K)
{
    __shared__ __nv_bfloat16 sAh[128 * APAD];
    __shared__ __nv_bfloat16 sAl[128 * APAD];
    __shared__ __nv_bfloat16 sBh[128 * APAD];
    __shared__ __nv_bfloat16 sBl[128 * APAD];

    int tid = threadIdx.x, lane = tid & 31, wid = tid >> 5;
    int m0 = blockIdx.y * 128, n0 = blockIdx.x * 128;
    int kPer = K / gridDim.z;
    int kBeg = blockIdx.z * kPer;
    Cm += (size_t)blockIdx.z * (size_t)M * ldc;

    int warp_m = wid & 1;       // 2 warps over M (64 rows each)
    int warp_n = wid >> 1;      // 4 warps over N (32 cols each)

    float acc[4][4][4];
    #pragma unroll
    for (int i = 0; i < 4; i++)
        #pragma unroll
        for (int j = 0; j < 4; j++)
            #pragma unroll
            for (int q = 0; q < 4; q++) acc[i][j][q] = 0.f;

    // loader mapping: 256 threads -> (row 0..127, k-half 0/16)
    int lrow = tid & 127;
    int lkh  = (tid >> 7) * 16;
    bool aok = (m0 + lrow) < M;
    bool bok = (n0 + lrow) < N;
    const float* Ap = A + (size_t)(m0 + lrow) * lda + kBeg + lkh;
    const float* Bp = Bm + (size_t)(n0 + lrow) * ldb + kBeg + lkh;

    for (int k0 = 0; k0 < kPer; k0 += KT) {
        __syncthreads();
        #pragma unroll
        for (int i = 0; i < 4; i++) {
            int sidx = lrow * APAD + lkh + i * 4;
            float4 av = aok ? *(const float4*)(Ap + k0 + i * 4) : make_float4(0.f, 0.f, 0.f, 0.f);
            uint32_t h0 = packbf(av.x, av.y), h1 = packbf(av.z, av.w);
            uint32_t l0 = packbf(av.x - bflo(h0), av.y - bfhi(h0));
            uint32_t l1 = packbf(av.z - bflo(h1), av.w - bfhi(h1));
            *(uint2*)&sAh[sidx] = make_uint2(h0, h1);
            *(uint2*)&sAl[sidx] = make_uint2(l0, l1);

            float4 bv = bok ? *(const float4*)(Bp + k0 + i * 4) : make_float4(0.f, 0.f, 0.f, 0.f);
            uint32_t bh0 = packbf(bv.x, bv.y), bh1 = packbf(bv.z, bv.w);
            uint32_t bl0 = packbf(bv.x - bflo(bh0), bv.y - bfhi(bh0));
            uint32_t bl1 = packbf(bv.z - bflo(bh1), bv.w - bfhi(bh1));
            *(uint2*)&sBh[sidx] = make_uint2(bh0, bh1);
            *(uint2*)&sBl[sidx] = make_uint2(bl0, bl1);
        }
        __syncthreads();

        #pragma unroll
        for (int ks = 0; ks < 2; ks++) {
            int kb = ks * 16 + (lane & 3) * 2;
            uint32_t ah[4][4], al[4][4], bh[4][2], bl[4][2];
            #pragma unroll
            for (int mi = 0; mi < 4; mi++) {
                int r = warp_m * 64 + mi * 16 + (lane >> 2);
                ah[mi][0] = *(const uint32_t*)&sAh[r * APAD + kb];
                ah[mi][1] = *(const uint32_t*)&sAh[(r + 8) * APAD + kb];
                ah[mi][2] = *(const uint32_t*)&sAh[r * APAD + kb + 8];
                ah[mi][3] = *(const uint32_t*)&sAh[(r + 8) * APAD + kb + 8];
                al[mi][0] = *(const uint32_t*)&sAl[r * APAD + kb];
                al[mi][1] = *(const uint32_t*)&sAl[(r + 8) * APAD + kb];
                al[mi][2] = *(const uint32_t*)&sAl[r * APAD + kb + 8];
                al[mi][3] = *(const uint32_t*)&sAl[(r + 8) * APAD + kb + 8];
            }
            #pragma unroll
            for (int ni = 0; ni < 4; ni++) {
                int r = warp_n * 32 + ni * 8 + (lane >> 2);
                bh[ni][0] = *(const uint32_t*)&sBh[r * APAD + kb];
                bh[ni][1] = *(const uint32_t*)&sBh[r * APAD + kb + 8];
                bl[ni][0] = *(const uint32_t*)&sBl[r * APAD + kb];
                bl[ni][1] = *(const uint32_t*)&sBl[r * APAD + kb + 8];
            }
            #pragma unroll
            for (int mi = 0; mi < 4; mi++)
                #pragma unroll
                for (int ni = 0; ni < 4; ni++) {
                    mma16816(acc[mi][ni], ah[mi], bh[ni]);
                    mma16816(acc[mi][ni], ah[mi], bl[ni]);
                    mma16816(acc[mi][ni], al[mi], bh[ni]);
                }
        }
    }

    // epilogue: c0=(m,n) c1=(m,n+1) c2=(m+8,n) c3=(m+8,n+1)
    #pragma unroll
    for (int mi = 0; mi < 4; mi++) {
        int m = m0 + warp_m * 64 + mi * 16 + (lane >> 2);
        #pragma unroll
        for (int ni = 0; ni < 4; ni++) {
            int n = n0 + warp_n * 32 + ni * 8 + (lane & 3) * 2;
            if (n < N) {
                float bx = 0.f, by = 0.f;
                if (bias) { bx = bias[n]; by = bias[n + 1]; }
                if (m < M) {
                    float2 o = make_float2(acc[mi][ni][0] + bx, acc[mi][ni][1] + by);
                    *(float2*)(Cm + (size_t)m * ldc + n) = o;
                }
                if (m + 8 < M) {
                    float2 o = make_float2(acc[mi][ni][2] + bx, acc[mi][ni][3] + by);
                    *(float2*)(Cm + (size_t)(m + 8) * ldc + n) = o;
                }
            }
        }
    }
}

// ---------------- small kernels ----------------

__global__ void mean_kernel(const float* __restrict__ img) {
    int w = (blockIdx.x * blockDim.x + threadIdx.x) >> 5;
    int lane = threadIdx.x & 31;
    if (w >= BB * CC) return;
    const float* p = img + (size_t)w * HWD;
    float s = 0.f;
    for (int k = lane; k < HWD; k += 32) s += p[k];
    #pragma unroll
    for (int o = 16; o; o >>= 1) s += __shfl_xor_sync(0xFFFFFFFFu, s, o);
    if (!lane) g_fm[w] = s * (1.0f / HWD);
}

__global__ void transpose_kernel(const float* __restrict__ img) {
    __shared__ float tile[32][33];
    int b = blockIdx.z;
    int k0 = blockIdx.x * 32, c0 = blockIdx.y * 32;
    int tx = threadIdx.x, ty = threadIdx.y;
    for (int i = ty; i < 32; i += 8) {
        int c = c0 + i, k = k0 + tx;
        tile[i][tx] = (c < CC && k < HWD) ? img[((size_t)b * CC + c) * HWD + k] : 0.f;
    }
    __syncthreads();
    for (int i = ty; i < 32; i += 8) {
        int k = k0 + i, c = c0 + tx;
        if (k < HWD && c < CC)
            g_featsT[((size_t)b * HWD + k) * CC + c] = tile[tx][i];
    }
}

__global__ void init_hc_kernel(const float* __restrict__ W_h0, const float* __restrict__ b_h0,
                               const float* __restrict__ W_c0, const float* __restrict__ b_c0) {
    int w = (blockIdx.x * blockDim.x + threadIdx.x) >> 5;
    int lane = threadIdx.x & 31;
    if (w >= BB * UU) return;
    int b = w / UU, u = w % UU;
    const float* fm = g_fm + b * CC;
    const float* wh = W_h0 + (size_t)u * CC;
    const float* wc = W_c0 + (size_t)u * CC;
    float sh = 0.f, sc = 0.f;
    for (int c = lane; c < CC; c += 32) {
        float f = fm[c];
        sh += f * wh[c];
        sc += f * wc[c];
    }
    #pragma unroll
    for (int o = 16; o; o >>= 1) {
        sh += __shfl_xor_sync(0xFFFFFFFFu, sh, o);
        sc += __shfl_xor_sync(0xFFFFFFFFu, sc, o);
    }
    if (!lane) {
        g_hid[w]  = sh + b_h0[u];
        g_cell[w] = sc + b_c0[u];
    }
}

__global__ void emb_kernel(const int* __restrict__ cap, const float* __restrict__ emb) {
    int w = (blockIdx.x * blockDim.x + threadIdx.x) >> 5;
    int lane = threadIdx.x & 31;
    if (w >= BB * TT) return;
    int idx = cap[w];
    const float* row = emb + (size_t)idx * EE;
    float v[8];
    float ss = 0.f;
    #pragma unroll
    for (int i = 0; i < 8; i++) { v[i] = row[lane + 32 * i]; ss += v[i] * v[i]; }
    #pragma unroll
    for (int o = 16; o; o >>= 1) ss += __shfl_xor_sync(0xFFFFFFFFu, ss, o);
    float norm = sqrtf(ss);
    float sc = fminf(1.0f, 5.0f / fmaxf(norm, 1e-12f));
    #pragma unroll
    for (int i = 0; i < 8; i++) g_capemb[(size_t)w * EE + lane + 32 * i] = v[i] * sc;
}

__global__ void wcat_kernel(const float* __restrict__ W_ih, const float* __restrict__ b_ih,
                            const float* __restrict__ W_hh, const float* __restrict__ b_hh) {
    int stride = gridDim.x * blockDim.x;
    int t0 = blockIdx.x * blockDim.x + threadIdx.x;
    for (int i = t0; i < G4 * XD; i += stride) {
        int j = i / XD, c = i - j * XD;
        g_Wcat[i] = (c < IHK) ? W_ih[(size_t)j * IHK + c]
                              : W_hh[(size_t)j * UU + (c - IHK)];
    }
    if (t0 < G4) g_bcat[t0] = b_ih[t0] + b_hh[t0];
}

// fused per-step: scores + softmax + attend + pack
__global__ void att_fused(const float* __restrict__ img, float* __restrict__ attn_out, int t) {
    __shared__ float hid_s[UU];
    __shared__ float w_s[HWD];
    __shared__ float red[256];
    int b = blockIdx.x, tid = threadIdx.x, wid = tid >> 5, lane = tid & 31;

    for (int u = tid; u < UU; u += 256) {
        float h = g_hid[b * UU + u];
        hid_s[u] = h;
        g_x[b * XD + IHK + u] = h;
    }
    __syncthreads();

    for (int k = wid; k < HWD; k += 8) {
        const float* kp = g_keys + ((size_t)b * HWD + k) * UU;
        float s = 0.f;
        for (int u = lane; u < UU; u += 32) s += hid_s[u] * kp[u];
        #pragma unroll
        for (int o = 16; o; o >>= 1) s += __shfl_xor_sync(0xFFFFFFFFu, s, o);
        if (!lane) w_s[k] = s * 0.044194173824159216f;
    }
    __syncthreads();

    float v = (tid < HWD) ? w_s[tid] : -1e30f;
    red[tid] = v;
    __syncthreads();
    for (int s = 128; s; s >>= 1) { if (tid < s) red[tid] = fmaxf(red[tid], red[tid + s]); __syncthreads(); }
    float mx = red[0];
    __syncthreads();
    float e = (tid < HWD) ? expf(v - mx) : 0.f;
    red[tid] = e;
    __syncthreads();
    for (int s = 128; s; s >>= 1) { if (tid < s) red[tid] += red[tid + s]; __syncthreads(); }
    float inv = 1.0f / red[0];
    if (tid < HWD) {
        float wv = e * inv;
        w_s[tid] = wv;
        if (attn_out) attn_out[((size_t)b * TT + t) * HWD + tid] = wv;
    }
    __syncthreads();

    for (int c = wid; c < CC; c += 8) {
        const float* ip = img + ((size_t)b * CC + c) * HWD;
        float s = 0.f;
        for (int k = lane; k < HWD; k += 32) s += w_s[k] * ip[k];
        #pragma unroll
        for (int o = 16; o; o >>= 1) s += __shfl_xor_sync(0xFFFFFFFFu, s, o);
        if (!lane) {
            g_x[b * XD + EE + c] = s;
            g_outs[((size_t)(b * TT + t)) * XD + UU + c] = s;
        }
    }

    for (int r = tid; r < EE; r += 256) {
        float e2 = g_capemb[((size_t)(b * TT + t)) * EE + r];
        g_x[b * XD + r] = e2;
        g_outs[((size_t)(b * TT + t)) * XD + UU + CC + r] = e2;
    }
}

// LSTM pointwise: sums split-K partials + bias
__global__ void lstm_kernel(int t) {
    int i = blockIdx.x * blockDim.x + threadIdx.x;
    if (i >= BB * UU) return;
    int b = i / UU, u = i - b * UU;
    float gi = g_bcat[u], gf = g_bcat[UU + u], gg = g_bcat[2 * UU + u], go = g_bcat[3 * UU + u];
    #pragma unroll
    for (int s = 0; s < KSPLIT; s++) {
        const float* p = g_gpart + ((size_t)s * BB + b) * G4;
        gi += p[u]; gf += p[UU + u]; gg += p[2 * UU + u]; go += p[3 * UU + u];
    }
    float si = 1.f / (1.f + expf(-gi));
    float sf = 1.f / (1.f + expf(-gf));
    float so = 1.f / (1.f + expf(-go));
    float c = sf * g_cell[i] + si * tanhf(gg);
    float h = so * tanhf(c);
    g_cell[i] = c;
    g_hid[i]  = h;
    g_outs[((size_t)(b * TT + t)) * XD + u] = h;
}

// ---------------- host ----------------
static float* symaddr(const void* sym) {
    void* p = nullptr;
    cudaGetSymbolAddress(&p, sym);
    return (float*)p;
}

extern "C" void kernel_launch(void* const* d_in, const int* in_sizes, int n_in,
                              void* d_out, int out_size) {
    const float* img   = (const float*)d_in[0];
    const int*   cap   = (const int*)d_in[1];
    const float* W_h0  = (const float*)d_in[2];
    const float* b_h0  = (const float*)d_in[3];
    const float* W_c0  = (const float*)d_in[4];
    const float* b_c0  = (const float*)d_in[5];
    const float* emb   = (const float*)d_in[6];
    const float* W_key = (const float*)d_in[7];
    const float* b_key = (const float*)d_in[8];
    const float* W_ih  = (const float*)d_in[9];
    const float* b_ih  = (const float*)d_in[10];
    const float* W_hh  = (const float*)d_in[11];
    const float* b_hh  = (const float*)d_in[12];
    const float* W_out = (const float*)d_in[13];
    const float* b_out = (const float*)d_in[14];
    float* out = (float*)d_out;

    float* p_featsT = symaddr(g_featsT);
    float* p_keys   = symaddr(g_keys);
    float* p_x      = symaddr(g_x);
    float* p_gpart  = symaddr(g_gpart);
    float* p_outs   = symaddr(g_outs);
    float* p_Wcat   = symaddr(g_Wcat);

    float* attn_out = (out_size >= LOGITS_SZ + ATTN_SZ) ? (out + LOGITS_SZ) : nullptr;

    mean_kernel<<<(BB * CC / 8), 256>>>(img);
    transpose_kernel<<<dim3(7, 16, BB), dim3(32, 8)>>>(img);
    init_hc_kernel<<<(BB * UU / 8), 256>>>(W_h0, b_h0, W_c0, b_c0);
    emb_kernel<<<(BB * TT + 7) / 8, 256>>>(cap, emb);
    wcat_kernel<<<1024, 256>>>(W_ih, b_ih, W_hh, b_hh);

    // keys = featsT @ W_key^T + b_key : M=12544, N=512, K=512
    hgemm<<<dim3(UU / 128, (BB * HWD) / 128, 1), 256>>>(
        p_featsT, CC, W_key, CC, b_key, p_keys, UU, BB * HWD, UU, CC);

    for (int t = 0; t < TT; t++) {
        att_fused<<<BB, 256>>>(img, attn_out, t);
        // gates partials = x @ Wcat^T (split-K=4) : M=64, N=2048, K=1280
        hgemm<<<dim3(G4 / 128, 1, KSPLIT), 256>>>(
            p_x, XD, p_Wcat, XD, nullptr, p_gpart, G4, BB, G4, XD);
        lstm_kernel<<<(BB * UU + 255) / 256, 256>>>(t);
    }

    // logits = outs @ W_out^T + b_out : M=1280, N=10000, K=1280
    hgemm<<<dim3((VV + 127) / 128, (BB * TT) / 128, 1), 256>>>(
        p_outs, XD, W_out, XD, b_out, out, VV, BB * TT, VV, XD);
}